// round 17
// baseline (speedup 1.0000x reference)
#include <cuda_runtime.h>
#include <cuda_bf16.h>
#include <stdint.h>
#include <math.h>

#define BATCH 2
#define NTOK  2048
#define CDIM  768
#define HEADS 12
#define DHEAD 64
#define HALF  64
#define SCALE 0.125f  /* 64^-0.5 */

// ---------------- scratch (device globals; no allocations allowed) ----------
__device__ float g_Q[(size_t)BATCH * HEADS * NTOK * DHEAD];
__device__ float g_K[(size_t)BATCH * HEADS * NTOK * DHEAD];
__device__ float g_V[(size_t)BATCH * HEADS * NTOK * DHEAD];
__device__ float g_O[(size_t)BATCH * NTOK * CDIM];

// ---------------- helpers ----------------------------------------------------
__device__ __forceinline__ uint32_t smem_u32(const void* p) {
    uint32_t a;
    asm("{ .reg .u64 t; cvta.to.shared.u64 t, %1; cvt.u32.u64 %0, t; }"
        : "=r"(a) : "l"(p));
    return a;
}
__device__ __forceinline__ void ldsm4(uint32_t* r, uint32_t addr) {
    asm volatile("ldmatrix.sync.aligned.m8n8.x4.shared.b16 {%0,%1,%2,%3}, [%4];"
                 : "=r"(r[0]), "=r"(r[1]), "=r"(r[2]), "=r"(r[3]) : "r"(addr));
}
__device__ __forceinline__ void mma16816(float* d, const uint32_t* a,
                                         const uint32_t* b) {
    asm volatile(
        "mma.sync.aligned.m16n8k16.row.col.f32.bf16.bf16.f32 "
        "{%0,%1,%2,%3}, {%4,%5,%6,%7}, {%8,%9}, {%0,%1,%2,%3};"
        : "+f"(d[0]), "+f"(d[1]), "+f"(d[2]), "+f"(d[3])
        : "r"(a[0]), "r"(a[1]), "r"(a[2]), "r"(a[3]), "r"(b[0]), "r"(b[1]));
}
__device__ __forceinline__ uint32_t bits2(__nv_bfloat162 v) {
    return *reinterpret_cast<uint32_t*>(&v);
}
__device__ __forceinline__ void split4(float4 v, uint2& hi, uint2& lo) {
    __nv_bfloat162 h01 = __floats2bfloat162_rn(v.x, v.y);
    __nv_bfloat162 h23 = __floats2bfloat162_rn(v.z, v.w);
    __nv_bfloat162 l01 = __floats2bfloat162_rn(v.x - __low2float(h01),
                                               v.y - __high2float(h01));
    __nv_bfloat162 l23 = __floats2bfloat162_rn(v.z - __low2float(h23),
                                               v.w - __high2float(h23));
    hi = make_uint2(bits2(h01), bits2(h23));
    lo = make_uint2(bits2(l01), bits2(l23));
}
__device__ __forceinline__ void split2(float a, float b, uint32_t& hi, uint32_t& lo) {
    __nv_bfloat162 h = __floats2bfloat162_rn(a, b);
    __nv_bfloat162 l = __floats2bfloat162_rn(a - __low2float(h), b - __high2float(h));
    hi = bits2(h);
    lo = bits2(l);
}

// ---------------- bf16x3 mma.sync GEMM: C[M,Nc] = A[M,768] @ B[Nc,768]^T -----
// MODE 0 (BN=256): A = x, scatter into g_Q/g_K/g_V; 8 warps, 2 warps/SMSP.
// MODE 1 (BN=128): A = g_O, C = d_out + bias; 4 warps (byte-equiv to R15).
// CTA tile 128 x BN, warp tile 64x64, warp grid 2 x (BN/64), threads = BN.
#define BK 32
#define SSTR 40
#define A_PL (128 * SSTR * 2)            /* 10240 : one A plane (hi or lo) */

template <int MODE, int BN>
__global__ void __launch_bounds__(BN) tcgemm(const float* __restrict__ A,
                                             const float* __restrict__ Bw,
                                             const float* __restrict__ bias,
                                             float* __restrict__ Cout) {
    constexpr int NW = BN / 64;          // warps in N (2 or 4)
    constexpr int B_PL = BN * SSTR * 2;  // one B plane
    constexpr int OFF_AL = A_PL;
    constexpr int OFF_BH = 2 * A_PL;
    constexpr int OFF_BL = 2 * A_PL + B_PL;
    constexpr int BUF = 2 * A_PL + 2 * B_PL;
    constexpr int AITER = 128 * 8 / BN;  // A staging iterations (8 or 4)
    constexpr int RSTEP = BN / 8;        // staged rows per iteration
    constexpr int NCHUNK = CDIM / BK;

    extern __shared__ __align__(128) char smem[];
    const int tid = threadIdx.x;
    const int wid = tid >> 5, lane = tid & 31;
    const int m0w = (wid / NW) * 64;
    const int n0w = (wid % NW) * 64;
    const int rowBase = blockIdx.y * 128;
    const int colBase = blockIdx.x * BN;
    const float* Asrc = (MODE == 1) ? (const float*)g_O : A;
    const uint32_t sbase = smem_u32(smem);

    const int sr = tid >> 3;            // 0..BN/8-1
    const int sc = (tid & 7) * 4;       // col (floats)

    float4 aR[AITER];
    auto ldgA = [&](int k0) {
#pragma unroll
        for (int u = 0; u < AITER; u++) {
            int r = u * RSTEP + sr;
            aR[u] = *reinterpret_cast<const float4*>(
                Asrc + (size_t)(rowBase + r) * CDIM + k0 + sc);
        }
    };

    float acc[4][8][4] = {};
    ldgA(0);

    for (int c = 0; c < NCHUNK; c++) {
        char* bufp = smem + (c & 1) * BUF;
        const uint32_t bufu = sbase + (uint32_t)(c & 1) * BUF;
        const int k0 = c * BK;

        // stage A from registers
#pragma unroll
        for (int u = 0; u < AITER; u++) {
            int r = u * RSTEP + sr;
            uint32_t off = (uint32_t)(r * SSTR + sc) * 2;
            uint2 hi, lo;
            split4(aR[u], hi, lo);
            *reinterpret_cast<uint2*>(bufp + off) = hi;
            *reinterpret_cast<uint2*>(bufp + OFF_AL + off) = lo;
        }
        // stage B directly (LDG -> split -> STS); weights are L2-hot
#pragma unroll
        for (int u = 0; u < 8; u++) {
            int r = u * RSTEP + sr;
            float4 v = *reinterpret_cast<const float4*>(
                Bw + (size_t)(colBase + r) * CDIM + k0 + sc);
            uint32_t off = (uint32_t)(r * SSTR + sc) * 2;
            uint2 hi, lo;
            split4(v, hi, lo);
            *reinterpret_cast<uint2*>(bufp + OFF_BH + off) = hi;
            *reinterpret_cast<uint2*>(bufp + OFF_BL + off) = lo;
        }
        __syncthreads();

        if (c + 1 < NCHUNK) ldgA((c + 1) * BK);

#pragma unroll
        for (int ks = 0; ks < 2; ks++) {
            const int k16 = ks * 16;
            uint32_t aHi[4][4], aLo[4][4], bHi[4][4], bLo[4][4];

            uint32_t aoff =
                bufu + (uint32_t)((m0w + (lane & 15)) * SSTR + k16 + (lane >> 4) * 8) * 2;
#pragma unroll
            for (int mi = 0; mi < 4; mi++) {
                ldsm4(aHi[mi], aoff + mi * (16 * SSTR * 2));
                ldsm4(aLo[mi], aoff + OFF_AL + mi * (16 * SSTR * 2));
            }
            {
                int g = lane >> 3, w8 = lane & 7;
                uint32_t boff = bufu + OFF_BH +
                                (uint32_t)((n0w + (g >> 1) * 8 + w8) * SSTR + k16 +
                                           (g & 1) * 8) * 2;
#pragma unroll
                for (int np = 0; np < 4; np++) {
                    ldsm4(bHi[np], boff + np * (16 * SSTR * 2));
                    ldsm4(bLo[np], boff + B_PL + np * (16 * SSTR * 2));
                }
            }
            // product-major: 32 independent accumulators between reuses
#pragma unroll
            for (int mi = 0; mi < 4; mi++)
#pragma unroll
                for (int ni = 0; ni < 8; ni++)
                    mma16816(acc[mi][ni], aHi[mi], &bHi[ni >> 1][(ni & 1) * 2]);
#pragma unroll
            for (int mi = 0; mi < 4; mi++)
#pragma unroll
                for (int ni = 0; ni < 8; ni++)
                    mma16816(acc[mi][ni], aHi[mi], &bLo[ni >> 1][(ni & 1) * 2]);
#pragma unroll
            for (int mi = 0; mi < 4; mi++)
#pragma unroll
                for (int ni = 0; ni < 8; ni++)
                    mma16816(acc[mi][ni], aLo[mi], &bHi[ni >> 1][(ni & 1) * 2]);
        }
        __syncthreads();
    }

    // Epilogue straight from registers.
#pragma unroll
    for (int mi = 0; mi < 4; mi++) {
        int m = rowBase + m0w + 16 * mi + (lane >> 2);
#pragma unroll
        for (int ni = 0; ni < 8; ni++) {
            int e = colBase + n0w + 8 * ni + (lane & 3) * 2;
            float2 v0 = make_float2(acc[mi][ni][0], acc[mi][ni][1]);
            float2 v1 = make_float2(acc[mi][ni][2], acc[mi][ni][3]);
            if (MODE == 0) {
                int tsel = e / CDIM;
                int rr = e - tsel * CDIM;
                int h = rr >> 6, d = rr & 63;
                float* dst = (tsel == 0) ? g_Q : ((tsel == 1) ? g_K : g_V);
                int bb = m >> 11, n = m & (NTOK - 1);
                size_t base = ((size_t)(bb * HEADS + h)) * NTOK;
                *reinterpret_cast<float2*>(&dst[(base + n) * DHEAD + d]) = v0;
                *reinterpret_cast<float2*>(&dst[(base + n + 8) * DHEAD + d]) = v1;
            } else {
                float2 bv = *reinterpret_cast<const float2*>(&bias[e]);
                v0.x += bv.x; v0.y += bv.y;
                v1.x += bv.x; v1.y += bv.y;
                *reinterpret_cast<float2*>(&Cout[(size_t)m * CDIM + e]) = v0;
                *reinterpret_cast<float2*>(&Cout[(size_t)(m + 8) * CDIM + e]) = v1;
            }
        }
    }
}

#define GSMEM_QKV (2 * (2 * A_PL + 2 * (256 * SSTR * 2)))  /* 122880 */
#define GSMEM_PRJ (2 * (2 * A_PL + 2 * (128 * SSTR * 2)))  /* 81920  */

// ---------------- Sliding-window attention (byte-identical to passing R16) ---
#define KSLOTS 192
#define QSTR 72
#define KSTR 72
#define PSTR 200
#define VSTR 200
#define SSTRIDE 196
#define OFF_QH 0
#define OFF_QL 9216
#define OFF_KH 18432
#define OFF_KL 46080
#define OFF_S  0
#define OFF_PH 51200
#define OFF_PL 76800
#define OFF_VTH 0
#define OFF_VTL 25600
#define ATT_SMEM 102400

__global__ void __launch_bounds__(256, 2) attn_mma() {
    extern __shared__ __align__(128) char sm[];
    const uint32_t sb = smem_u32(sm);
    const int tid = threadIdx.x;
    const int wid = tid >> 5, lane = tid & 31;
    const int q0 = blockIdx.x * 64;
    const int bh = blockIdx.y;
    const int kstart = q0 - HALF;

    const float* Qg = g_Q + (size_t)bh * NTOK * DHEAD;
    const float* Kg = g_K + (size_t)bh * NTOK * DHEAD;
    const float* Vg = g_V + (size_t)bh * NTOK * DHEAD;

    // ---- phase 1: stage Q and K only ----
    for (int idx = tid; idx < 64 * 16; idx += 256) {
        int q = idx >> 4, d4 = (idx & 15) << 2;
        float4 v = *reinterpret_cast<const float4*>(&Qg[(size_t)(q0 + q) * DHEAD + d4]);
        uint2 hi, lo;
        split4(v, hi, lo);
        uint32_t off = (uint32_t)(q * QSTR + d4) * 2;
        *reinterpret_cast<uint2*>(sm + OFF_QH + off) = hi;
        *reinterpret_cast<uint2*>(sm + OFF_QL + off) = lo;
    }
    for (int idx = tid; idx < KSLOTS * 16; idx += 256) {
        int s = idx >> 4, d4 = (idx & 15) << 2;
        int j = kstart + s;
        float4 kv = make_float4(0.f, 0.f, 0.f, 0.f);
        if (j >= 0 && j < NTOK)
            kv = *reinterpret_cast<const float4*>(&Kg[(size_t)j * DHEAD + d4]);
        uint2 hi, lo;
        split4(kv, hi, lo);
        uint32_t off = (uint32_t)(s * KSTR + d4) * 2;
        *reinterpret_cast<uint2*>(sm + OFF_KH + off) = hi;
        *reinterpret_cast<uint2*>(sm + OFF_KL + off) = lo;
    }
    __syncthreads();

    // ---- QK^T: warp grid 2x4 (m 2x32, n 4x48) ----
    const int wm = (wid >> 2) * 32;
    const int wn = (wid & 3) * 48;
    float sacc[2][6][4] = {};
    {
        const int g = lane >> 3, w8 = lane & 7;
#pragma unroll
        for (int ks = 0; ks < 4; ks++) {
            const int k16 = ks * 16;
            uint32_t qh[2][4], ql[2][4], kh[3][4], kl[3][4];
            uint32_t aoff = sb + OFF_QH +
                (uint32_t)((wm + (lane & 15)) * QSTR + k16 + (lane >> 4) * 8) * 2;
#pragma unroll
            for (int mi = 0; mi < 2; mi++) {
                ldsm4(qh[mi], aoff + mi * (16 * QSTR * 2));
                ldsm4(ql[mi], aoff + (OFF_QL - OFF_QH) + mi * (16 * QSTR * 2));
            }
            uint32_t boff = sb + OFF_KH +
                (uint32_t)((wn + (g >> 1) * 8 + w8) * KSTR + k16 + (g & 1) * 8) * 2;
#pragma unroll
            for (int np = 0; np < 3; np++) {
                ldsm4(kh[np], boff + np * (16 * KSTR * 2));
                ldsm4(kl[np], boff + (OFF_KL - OFF_KH) + np * (16 * KSTR * 2));
            }
#pragma unroll
            for (int mi = 0; mi < 2; mi++)
#pragma unroll
                for (int nt = 0; nt < 6; nt++)
                    mma16816(sacc[mi][nt], qh[mi], &kh[nt >> 1][(nt & 1) * 2]);
#pragma unroll
            for (int mi = 0; mi < 2; mi++)
#pragma unroll
                for (int nt = 0; nt < 6; nt++)
                    mma16816(sacc[mi][nt], qh[mi], &kl[nt >> 1][(nt & 1) * 2]);
#pragma unroll
            for (int mi = 0; mi < 2; mi++)
#pragma unroll
                for (int nt = 0; nt < 6; nt++)
                    mma16816(sacc[mi][nt], ql[mi], &kh[nt >> 1][(nt & 1) * 2]);
        }
    }
    __syncthreads();  // Q/K reads done; region becomes S

    // ---- scale + mask, write S fp32 (at offset 0, over dead Q/K) ----
    float* S = (float*)(sm + OFF_S);
#pragma unroll
    for (int mi = 0; mi < 2; mi++) {
        int qA = wm + 16 * mi + (lane >> 2);
#pragma unroll
        for (int nt = 0; nt < 6; nt++) {
            int s0 = wn + 8 * nt + (lane & 3) * 2;
#pragma unroll
            for (int half = 0; half < 2; half++) {
                int q = qA + half * 8;
#pragma unroll
                for (int e = 0; e < 2; e++) {
                    int s = s0 + e;
                    int kj = kstart + s;
                    int diff = q + HALF - s;
                    bool ok = (kj >= 0) & (kj < NTOK) & (diff >= -HALF) & (diff <= HALF);
                    S[q * SSTRIDE + s] =
                        ok ? sacc[mi][nt][half * 2 + e] * SCALE : -3.0e38f;
                }
            }
        }
    }
    __syncthreads();

    // ---- softmax (S -> registers), then P stores + VT build ----
    {
        const int row = tid >> 2, part = tid & 3;
        const float* srow = S + row * SSTRIDE + part * 48;
        float vals[48];
#pragma unroll
        for (int i = 0; i < 12; i++) {
            float4 v = *reinterpret_cast<const float4*>(srow + 4 * i);
            vals[4 * i] = v.x; vals[4 * i + 1] = v.y;
            vals[4 * i + 2] = v.z; vals[4 * i + 3] = v.w;
        }
        float mx = -3.0e38f;
#pragma unroll
        for (int i = 0; i < 48; i++) mx = fmaxf(mx, vals[i]);
        mx = fmaxf(mx, __shfl_xor_sync(0xffffffff, mx, 1));
        mx = fmaxf(mx, __shfl_xor_sync(0xffffffff, mx, 2));
        float sum = 0.f;
#pragma unroll
        for (int i = 0; i < 48; i++) {
            vals[i] = __expf(vals[i] - mx);
            sum += vals[i];
        }
        sum += __shfl_xor_sync(0xffffffff, sum, 1);
        sum += __shfl_xor_sync(0xffffffff, sum, 2);
        float inv = __fdividef(1.f, sum);
        __syncthreads();  // all S reads complete; S region becomes VT
        uint32_t pbase = (uint32_t)(row * PSTR + part * 48) * 2;
#pragma unroll
        for (int i = 0; i < 24; i++) {
            uint32_t h, l;
            split2(vals[2 * i] * inv, vals[2 * i + 1] * inv, h, l);
            *reinterpret_cast<uint32_t*>(sm + OFF_PH + pbase + 4 * i) = h;
            *reinterpret_cast<uint32_t*>(sm + OFF_PL + pbase + 4 * i) = l;
        }
    }
    // VT build: reload V from gmem (L2-hot), split, store transposed
    for (int idx = tid; idx < KSLOTS * 16; idx += 256) {
        int s = idx >> 4, d4 = (idx & 15) << 2;
        int j = kstart + s;
        float4 vv = make_float4(0.f, 0.f, 0.f, 0.f);
        if (j >= 0 && j < NTOK)
            vv = *reinterpret_cast<const float4*>(&Vg[(size_t)j * DHEAD + d4]);
        float vf[4] = {vv.x, vv.y, vv.z, vv.w};
#pragma unroll
        for (int i = 0; i < 4; i++) {
            __nv_bfloat16 h = __float2bfloat16_rn(vf[i]);
            __nv_bfloat16 l = __float2bfloat16_rn(vf[i] - __bfloat162float(h));
            ((__nv_bfloat16*)(sm + OFF_VTH))[(d4 + i) * VSTR + s] = h;
            ((__nv_bfloat16*)(sm + OFF_VTL))[(d4 + i) * VSTR + s] = l;
        }
    }
    __syncthreads();

    // ---- PV: warp grid 2x4 (m 2x32, n(d) 4x16) ----
    const int wn2 = (wid & 3) * 16;
    float facc[2][2][4] = {};
    {
        const int g = lane >> 3, w8 = lane & 7;
#pragma unroll
        for (int ks = 0; ks < 12; ks++) {
            const int k16 = ks * 16;
            uint32_t ph[2][4], pl[2][4], vh[4], vl[4];
            uint32_t aoff = sb + OFF_PH +
                (uint32_t)((wm + (lane & 15)) * PSTR + k16 + (lane >> 4) * 8) * 2;
#pragma unroll
            for (int mi = 0; mi < 2; mi++) {
                ldsm4(ph[mi], aoff + mi * (16 * PSTR * 2));
                ldsm4(pl[mi], aoff + (OFF_PL - OFF_PH) + mi * (16 * PSTR * 2));
            }
            uint32_t boff = sb + OFF_VTH +
                (uint32_t)((wn2 + (g >> 1) * 8 + w8) * VSTR + k16 + (g & 1) * 8) * 2;
            ldsm4(vh, boff);
            ldsm4(vl, boff + (OFF_VTL - OFF_VTH));
#pragma unroll
            for (int mi = 0; mi < 2; mi++)
#pragma unroll
                for (int nt = 0; nt < 2; nt++)
                    mma16816(facc[mi][nt], ph[mi], &vh[nt * 2]);
#pragma unroll
            for (int mi = 0; mi < 2; mi++)
#pragma unroll
                for (int nt = 0; nt < 2; nt++)
                    mma16816(facc[mi][nt], ph[mi], &vl[nt * 2]);
#pragma unroll
            for (int mi = 0; mi < 2; mi++)
#pragma unroll
                for (int nt = 0; nt < 2; nt++)
                    mma16816(facc[mi][nt], pl[mi], &vh[nt * 2]);
        }
    }

    // ---- epilogue -> g_O [B,N,C] ----
    const int b = bh / HEADS, h = bh - b * HEADS;
#pragma unroll
    for (int mi = 0; mi < 2; mi++) {
        int n = q0 + wm + 16 * mi + (lane >> 2);
#pragma unroll
        for (int nt = 0; nt < 2; nt++) {
            int d = wn2 + 8 * nt + (lane & 3) * 2;
            float* p0 = &g_O[((size_t)b * NTOK + n) * CDIM + h * DHEAD + d];
            float* p1 = &g_O[((size_t)b * NTOK + n + 8) * CDIM + h * DHEAD + d];
            *reinterpret_cast<float2*>(p0) = make_float2(facc[mi][nt][0], facc[mi][nt][1]);
            *reinterpret_cast<float2*>(p1) = make_float2(facc[mi][nt][2], facc[mi][nt][3]);
        }
    }
}

// ---------------- launch ----------------------------------------------------
extern "C" void kernel_launch(void* const* d_in, const int* in_sizes, int n_in,
                              void* d_out, int out_size) {
    (void)in_sizes; (void)n_in; (void)out_size;
    const float* x      = (const float*)d_in[0];
    const float* w_qkv  = (const float*)d_in[1];
    const float* w_proj = (const float*)d_in[2];
    const float* b_proj = (const float*)d_in[3];
    float* out = (float*)d_out;

    cudaFuncSetAttribute(tcgemm<0, 256>, cudaFuncAttributeMaxDynamicSharedMemorySize,
                         GSMEM_QKV);
    cudaFuncSetAttribute(tcgemm<1, 128>, cudaFuncAttributeMaxDynamicSharedMemorySize,
                         GSMEM_PRJ);
    cudaFuncSetAttribute(attn_mma, cudaFuncAttributeMaxDynamicSharedMemorySize,
                         ATT_SMEM);

    // 1) QKV projection: 128x256 CTA tile, 8 warps (2 warps/SMSP)
    tcgemm<0, 256><<<dim3(3 * CDIM / 256, BATCH * NTOK / 128), 256, GSMEM_QKV>>>(
        x, w_qkv, nullptr, nullptr);

    // 2) Sliding-window attention (2 CTAs/SM via smem time-multiplexing)
    attn_mma<<<dim3(NTOK / 64, BATCH * HEADS), 256, ATT_SMEM>>>();

    // 3) Output projection + bias: 128x128 CTA tile (known-good shape)
    tcgemm<1, 128><<<dim3(CDIM / 128, BATCH * NTOK / 128), 128, GSMEM_PRJ>>>(
        nullptr, w_proj, b_proj, out);
}